// round 1
// baseline (speedup 1.0000x reference)
#include <cuda_runtime.h>
#include <cstdint>
#include <cstddef>

// LowRankINRLayer: out = relu( (x @ v^T) @ W^T )
//   x [16, 8192, 512] f32, v [16, 32, 512] f32, W [512, 32] f32 -> out [16, 8192, 512] f32
//
// Fused two-stage tf32 mma.sync kernel.
//   GEMM1: per-CTA x-tile (128x512) @ v[b]^T (512x32) -> C1 (128x32), accum in regs
//   GEMM2: C1 (128x32) @ W^T (32x512) -> out tile (128x512), relu, coalesced stores
// All mma operands pass through cvt.rna.tf32.f32 (round-to-nearest; HW truncation
// would bias the K=512 reduction by ~1e-3 and fail the 1e-3 threshold).

namespace {

constexpr int kB  = 16;
constexpr int kN  = 8192;
constexpr int kDI = 512;
constexpr int kDO = 512;
constexpr int kR  = 32;

constexpr int TM      = 128;        // rows per CTA
constexpr int KC      = 64;         // K chunk staged per iteration
constexpr int NCH     = kDI / KC;   // 8 chunks
constexpr int THREADS = 256;        // 8 warps, 16 rows each

// SMEM strides in 32-bit words. All are ≡ 4 (mod 32) so the per-fragment LDS
// pattern (bank = 4*(lane/4) + lane%4 + const) is bank-conflict-free, and all
// are multiples of 4 so float4/uint4 accesses stay 16B-aligned.
constexpr int XS_STRIDE = KC + 4;    // 68
constexpr int VS_STRIDE = kDI + 4;   // 516
constexpr int WS_STRIDE = kR + 4;    // 36

constexpr int XS_BUF     = TM * XS_STRIDE;            // 8704 words per buffer
constexpr int VS_OFF     = 2 * XS_BUF;                // 17408
constexpr int WS_OFF     = VS_OFF + kR * VS_STRIDE;   // 33920
constexpr int SMEM_WORDS = WS_OFF + kDO * WS_STRIDE;  // 52352
constexpr int SMEM_BYTES = SMEM_WORDS * 4;            // 209408 B < 227 KB

__device__ __forceinline__ unsigned f2tf(float f) {
    unsigned u;
    asm("cvt.rna.tf32.f32 %0, %1;" : "=r"(u) : "f"(f));
    return u;
}

__device__ __forceinline__ void mma_tf32(float& d0, float& d1, float& d2, float& d3,
                                         unsigned a0, unsigned a1, unsigned a2, unsigned a3,
                                         unsigned b0, unsigned b1) {
    asm volatile(
        "mma.sync.aligned.m16n8k8.row.col.f32.tf32.tf32.f32 "
        "{%0,%1,%2,%3}, {%4,%5,%6,%7}, {%8,%9}, {%0,%1,%2,%3};"
        : "+f"(d0), "+f"(d1), "+f"(d2), "+f"(d3)
        : "r"(a0), "r"(a1), "r"(a2), "r"(a3), "r"(b0), "r"(b1));
}

__global__ void __launch_bounds__(THREADS, 1)
lowrank_inr_kernel(const float* __restrict__ x,
                   const float* __restrict__ v,
                   const float* __restrict__ W,
                   float* __restrict__ out)
{
    extern __shared__ unsigned sm[];
    unsigned* xs = sm;             // [2][TM][XS_STRIDE] tf32 x chunks (double buffer)
    unsigned* vs = sm + VS_OFF;    // [32][VS_STRIDE]    tf32 v[b]
    unsigned* ws = sm + WS_OFF;    // [512][WS_STRIDE]   tf32 W

    const int tid  = threadIdx.x;
    const int lane = tid & 31;
    const int warp = tid >> 5;
    const int g    = lane >> 2;    // group id (row within fragment)
    const int t4   = lane & 3;     // thread-in-group (col within fragment)

    const int b  = blockIdx.x >> 6;          // 64 tiles per batch
    const int m0 = (blockIdx.x & 63) * TM;

    const float* xg = x + ((size_t)b * kN + m0) * kDI;
    const float* vg = v + (size_t)b * kR * kDI;

    // ---- stage v[b] (32 x 512) as tf32 ----
    #pragma unroll
    for (int i = 0; i < 16; i++) {
        int idx = tid + THREADS * i;          // 0..4095 float4s
        int row = idx >> 7, c4 = idx & 127;
        float4 f = *reinterpret_cast<const float4*>(vg + row * kDI + c4 * 4);
        uint4 u = make_uint4(f2tf(f.x), f2tf(f.y), f2tf(f.z), f2tf(f.w));
        *reinterpret_cast<uint4*>(vs + row * VS_STRIDE + c4 * 4) = u;
    }
    // ---- stage W (512 x 32) as tf32 ----
    #pragma unroll
    for (int i = 0; i < 16; i++) {
        int idx = tid + THREADS * i;          // 0..4095 float4s
        int row = idx >> 3, c4 = idx & 7;
        float4 f = *reinterpret_cast<const float4*>(W + row * kR + c4 * 4);
        uint4 u = make_uint4(f2tf(f.x), f2tf(f.y), f2tf(f.z), f2tf(f.w));
        *reinterpret_cast<uint4*>(ws + row * WS_STRIDE + c4 * 4) = u;
    }

    // ---- prologue: load x chunk 0 into regs, store to buffer 0 ----
    float4 nx[8];
    #pragma unroll
    for (int i = 0; i < 8; i++) {
        int idx = tid + THREADS * i;          // 2048 float4s per chunk
        int row = idx >> 4, c4 = idx & 15;
        nx[i] = *reinterpret_cast<const float4*>(xg + (size_t)row * kDI + c4 * 4);
    }
    #pragma unroll
    for (int i = 0; i < 8; i++) {
        int idx = tid + THREADS * i;
        int row = idx >> 4, c4 = idx & 15;
        uint4 u = make_uint4(f2tf(nx[i].x), f2tf(nx[i].y), f2tf(nx[i].z), f2tf(nx[i].w));
        *reinterpret_cast<uint4*>(xs + row * XS_STRIDE + c4 * 4) = u;
    }
    __syncthreads();

    // ---- GEMM1: acc1[nb][0..3] = x_tile @ v^T, per warp m=16, n=32 ----
    float acc1[4][4] = {};
    const int mw = warp * 16;

    for (int c = 0; c < NCH; c++) {
        if (c + 1 < NCH) {          // prefetch next chunk (global -> regs)
            #pragma unroll
            for (int i = 0; i < 8; i++) {
                int idx = tid + THREADS * i;
                int row = idx >> 4, c4 = idx & 15;
                nx[i] = *reinterpret_cast<const float4*>(
                    xg + (size_t)row * kDI + (c + 1) * KC + c4 * 4);
            }
        }
        const unsigned* xb = xs + (c & 1) * XS_BUF;
        #pragma unroll
        for (int ks = 0; ks < KC / 8; ks++) {
            const int k0 = ks * 8;
            unsigned a0 = xb[(mw + g) * XS_STRIDE + k0 + t4];
            unsigned a1 = xb[(mw + g + 8) * XS_STRIDE + k0 + t4];
            unsigned a2 = xb[(mw + g) * XS_STRIDE + k0 + t4 + 4];
            unsigned a3 = xb[(mw + g + 8) * XS_STRIDE + k0 + t4 + 4];
            #pragma unroll
            for (int nb = 0; nb < 4; nb++) {
                const unsigned* vrow = vs + (nb * 8 + g) * VS_STRIDE + c * KC + k0 + t4;
                mma_tf32(acc1[nb][0], acc1[nb][1], acc1[nb][2], acc1[nb][3],
                         a0, a1, a2, a3, vrow[0], vrow[4]);
            }
        }
        __syncthreads();
        if (c + 1 < NCH) {          // store prefetched chunk to other buffer
            const int buf = (c + 1) & 1;
            #pragma unroll
            for (int i = 0; i < 8; i++) {
                int idx = tid + THREADS * i;
                int row = idx >> 4, c4 = idx & 15;
                uint4 u = make_uint4(f2tf(nx[i].x), f2tf(nx[i].y), f2tf(nx[i].z), f2tf(nx[i].w));
                *reinterpret_cast<uint4*>(xs + buf * XS_BUF + row * XS_STRIDE + c4 * 4) = u;
            }
            __syncthreads();
        }
    }

    // ---- accumulator -> GEMM2 A-fragment relayout (intra-quad shuffles) ----
    // C1 accum holds cols {2*t4, 2*t4+1}; A-frag needs cols {t4, t4+4}.
    unsigned af[4][4];
    const unsigned FULL = 0xffffffffu;
    #pragma unroll
    for (int ks = 0; ks < 4; ks++) {    // k-step r0 = 8*ks lives in acc1[ks]
        float c0 = acc1[ks][0], c1 = acc1[ks][1];
        float c2 = acc1[ks][2], c3 = acc1[ks][3];
        int srcA = (lane & ~3) | (t4 >> 1);   // owner of col t4
        int srcB = srcA + 2;                  // owner of col t4+4
        bool odd = (t4 & 1) != 0;
        float x00 = __shfl_sync(FULL, c0, srcA);
        float x01 = __shfl_sync(FULL, c1, srcA);
        float y00 = __shfl_sync(FULL, c2, srcA);
        float y01 = __shfl_sync(FULL, c3, srcA);
        float x20 = __shfl_sync(FULL, c0, srcB);
        float x21 = __shfl_sync(FULL, c1, srcB);
        float y20 = __shfl_sync(FULL, c2, srcB);
        float y21 = __shfl_sync(FULL, c3, srcB);
        af[ks][0] = f2tf(odd ? x01 : x00);    // (row g,   col r0+t4)
        af[ks][1] = f2tf(odd ? y01 : y00);    // (row g+8, col r0+t4)
        af[ks][2] = f2tf(odd ? x21 : x20);    // (row g,   col r0+4+t4)
        af[ks][3] = f2tf(odd ? y21 : y20);    // (row g+8, col r0+4+t4)
    }

    // ---- GEMM2: out_tile = relu(C1 @ W^T), 8 o-cols per mma block ----
    float* obase = out + ((size_t)b * kN + m0 + mw + g) * kDO;
    #pragma unroll 2
    for (int ob = 0; ob < kDO / 8; ob++) {
        const int o0 = ob * 8;
        float d0 = 0.f, d1 = 0.f, d2 = 0.f, d3 = 0.f;
        #pragma unroll
        for (int ks = 0; ks < 4; ks++) {
            const unsigned* wrow = ws + (o0 + g) * WS_STRIDE + ks * 8 + t4;
            mma_tf32(d0, d1, d2, d3,
                     af[ks][0], af[ks][1], af[ks][2], af[ks][3],
                     wrow[0], wrow[4]);
        }
        float2 lo = make_float2(fmaxf(d0, 0.f), fmaxf(d1, 0.f));
        float2 hi = make_float2(fmaxf(d2, 0.f), fmaxf(d3, 0.f));
        *reinterpret_cast<float2*>(obase + o0 + 2 * t4) = lo;              // row g
        *reinterpret_cast<float2*>(obase + 8 * kDO + o0 + 2 * t4) = hi;    // row g+8
    }
}

} // namespace

extern "C" void kernel_launch(void* const* d_in, const int* in_sizes, int n_in,
                              void* d_out, int out_size) {
    (void)in_sizes; (void)n_in; (void)out_size;
    const float* x = (const float*)d_in[0];
    const float* v = (const float*)d_in[1];
    const float* W = (const float*)d_in[2];
    float* out = (float*)d_out;

    cudaFuncSetAttribute(lowrank_inr_kernel,
                         cudaFuncAttributeMaxDynamicSharedMemorySize, SMEM_BYTES);
    lowrank_inr_kernel<<<kB * (kN / TM), THREADS, SMEM_BYTES>>>(x, v, W, out);
}

// round 2
// speedup vs baseline: 1.3188x; 1.3188x over previous
#include <cuda_runtime.h>
#include <cstdint>
#include <cstddef>

// LowRankINRLayer: out = relu( (x @ v^T) @ W^T )
//   x [16, 8192, 512] f32, v [16, 32, 512] f32, W [512, 32] f32 -> out [16, 8192, 512] f32
//
// Round 2: 4-stage cp.async pipeline (x and v K-chunks, raw f32), tf32 mma.sync,
// W register-resident per warp (o-column split in GEMM2), C1 through smem
// (reuses pipeline buffer 0). 162 KB smem, 512 threads, 16 warps/SM.

namespace {

constexpr int kB  = 16;
constexpr int kN  = 8192;
constexpr int kDI = 512;
constexpr int kDO = 512;
constexpr int kR  = 32;

constexpr int TM      = 256;          // rows per CTA
constexpr int KC      = 32;           // K-chunk per pipeline stage
constexpr int NCH     = kDI / KC;     // 16 chunks
constexpr int STAGES  = 4;
constexpr int THREADS = 512;          // 16 warps

// strides in words; ≡ 4 (mod 32) -> conflict-free fragment LDS, 16B-aligned rows
constexpr int XST = KC + 4;                     // 36
constexpr int XBUF = TM * XST;                  // 9216 words / stage
constexpr int VBUF = kR * XST;                  // 1152 words / stage
constexpr int VS_OFF = STAGES * XBUF;           // 36864
constexpr int SMEM_WORDS = VS_OFF + STAGES * VBUF;   // 41472
constexpr int SMEM_BYTES = SMEM_WORDS * 4;           // 165888 B

__device__ __forceinline__ unsigned f2tf(float f) {
    unsigned u;
    asm("cvt.rna.tf32.f32 %0, %1;" : "=r"(u) : "f"(f));
    return u;
}

__device__ __forceinline__ void mma_tf32(float& d0, float& d1, float& d2, float& d3,
                                         unsigned a0, unsigned a1, unsigned a2, unsigned a3,
                                         unsigned b0, unsigned b1) {
    asm volatile(
        "mma.sync.aligned.m16n8k8.row.col.f32.tf32.tf32.f32 "
        "{%0,%1,%2,%3}, {%4,%5,%6,%7}, {%8,%9}, {%0,%1,%2,%3};"
        : "+f"(d0), "+f"(d1), "+f"(d2), "+f"(d3)
        : "r"(a0), "r"(a1), "r"(a2), "r"(a3), "r"(b0), "r"(b1));
}

__device__ __forceinline__ void cp16(unsigned dst_smem, const float* src) {
    asm volatile("cp.async.cg.shared.global [%0], [%1], 16;"
                 :: "r"(dst_smem), "l"(src) : "memory");
}

__global__ void __launch_bounds__(THREADS, 1)
lowrank_inr_kernel(const float* __restrict__ x,
                   const float* __restrict__ v,
                   const float* __restrict__ W,
                   float* __restrict__ out)
{
    extern __shared__ float smf[];
    const unsigned sbase = (unsigned)__cvta_generic_to_shared(smf);

    const int tid  = threadIdx.x;
    const int lane = tid & 31;
    const int warp = tid >> 5;             // 0..15
    const int g    = lane >> 2;            // fragment row
    const int t4   = lane & 3;             // fragment col

    const int b  = blockIdx.x >> 5;        // 32 tiles of 256 rows per batch
    const int m0 = (blockIdx.x & 31) * TM;

    const float* xg = x + ((size_t)b * kN + m0) * kDI;
    const float* vg = v + (size_t)b * kR * kDI;

    // x mapping: 4 cp.async/thread/chunk; v mapping: tid<256 do 1 op
    const int xrow0 = tid >> 3;            // +64 per i
    const int xc4   = (tid & 7) * 4;
    const int vrow  = tid >> 3;            // tid<256: rows 0..31
    const int vc4   = (tid & 7) * 4;

    auto issue_chunk = [&](int c) {
        const int st = c & (STAGES - 1);
        const unsigned xd = sbase + (unsigned)(st * XBUF) * 4u;
        #pragma unroll
        for (int i = 0; i < 4; i++) {
            const int row = xrow0 + 64 * i;
            cp16(xd + (unsigned)(row * XST + xc4) * 4u,
                 xg + (size_t)row * kDI + c * KC + xc4);
        }
        if (tid < 256) {
            const unsigned vd = sbase + (unsigned)(VS_OFF + st * VBUF) * 4u;
            cp16(vd + (unsigned)(vrow * XST + vc4) * 4u,
                 vg + (size_t)vrow * kDI + c * KC + vc4);
        }
        asm volatile("cp.async.commit_group;" ::: "memory");
    };

    // ---- prologue: get DRAM moving ----
    issue_chunk(0);
    issue_chunk(1);
    issue_chunk(2);

    // ---- W fragments, register-resident: warp owns o-cols [warp*32, warp*32+32) ----
    const int oc0 = warp * 32;
    unsigned wf[4][4][2];
    #pragma unroll
    for (int ob = 0; ob < 4; ob++) {
        const float* wrow = W + (size_t)(oc0 + ob * 8 + g) * kR;
        #pragma unroll
        for (int ks = 0; ks < 4; ks++) {
            wf[ob][ks][0] = f2tf(wrow[ks * 8 + t4]);
            wf[ob][ks][1] = f2tf(wrow[ks * 8 + t4 + 4]);
        }
    }

    // ---- GEMM1 mainloop: acc1 = x_tile @ v^T (per warp: m=16 rows, n=32) ----
    float acc1[4][4] = {};
    const int mw = warp * 16;

    for (int c = 0; c < NCH; ++c) {
        if (c < NCH - 2)        asm volatile("cp.async.wait_group 2;" ::: "memory");
        else if (c == NCH - 2)  asm volatile("cp.async.wait_group 1;" ::: "memory");
        else                    asm volatile("cp.async.wait_group 0;" ::: "memory");
        __syncthreads();   // chunk c ready; chunk c-1 fully consumed by all warps

        if (c + 3 < NCH) issue_chunk(c + 3);

        const float* xb = smf + (c & (STAGES - 1)) * XBUF;
        const float* vb = smf + VS_OFF + (c & (STAGES - 1)) * VBUF;
        #pragma unroll
        for (int ks = 0; ks < KC / 8; ks++) {
            const int k0 = ks * 8;
            unsigned a0 = f2tf(xb[(mw + g)     * XST + k0 + t4]);
            unsigned a1 = f2tf(xb[(mw + g + 8) * XST + k0 + t4]);
            unsigned a2 = f2tf(xb[(mw + g)     * XST + k0 + t4 + 4]);
            unsigned a3 = f2tf(xb[(mw + g + 8) * XST + k0 + t4 + 4]);
            #pragma unroll
            for (int nb = 0; nb < 4; nb++) {
                unsigned b0 = f2tf(vb[(nb * 8 + g) * XST + k0 + t4]);
                unsigned b1 = f2tf(vb[(nb * 8 + g) * XST + k0 + t4 + 4]);
                mma_tf32(acc1[nb][0], acc1[nb][1], acc1[nb][2], acc1[nb][3],
                         a0, a1, a2, a3, b0, b1);
            }
        }
    }

    // ---- C1 (256 x 32) to smem, reusing pipeline buffer 0 ----
    __syncthreads();                 // everyone done with last chunk's buffers
    float* c1 = smf;                 // stride XST
    #pragma unroll
    for (int nb = 0; nb < 4; nb++) {
        *reinterpret_cast<float2*>(&c1[(mw + g)     * XST + nb * 8 + 2 * t4]) =
            make_float2(acc1[nb][0], acc1[nb][1]);
        *reinterpret_cast<float2*>(&c1[(mw + g + 8) * XST + nb * 8 + 2 * t4]) =
            make_float2(acc1[nb][2], acc1[nb][3]);
    }
    __syncthreads();

    // ---- GEMM2: out = relu(C1 @ W^T); warp covers all 256 rows x its 32 o-cols ----
    float* obase = out + ((size_t)b * kN + m0) * kDO;
    #pragma unroll 1
    for (int mb = 0; mb < TM / 16; mb++) {
        const int r0 = mb * 16 + g;
        unsigned a[4][4];
        #pragma unroll
        for (int ks = 0; ks < 4; ks++) {
            a[ks][0] = f2tf(c1[r0       * XST + ks * 8 + t4]);
            a[ks][1] = f2tf(c1[(r0 + 8) * XST + ks * 8 + t4]);
            a[ks][2] = f2tf(c1[r0       * XST + ks * 8 + t4 + 4]);
            a[ks][3] = f2tf(c1[(r0 + 8) * XST + ks * 8 + t4 + 4]);
        }
        #pragma unroll
        for (int ob = 0; ob < 4; ob++) {
            float d0 = 0.f, d1 = 0.f, d2 = 0.f, d3 = 0.f;
            #pragma unroll
            for (int ks = 0; ks < 4; ks++)
                mma_tf32(d0, d1, d2, d3,
                         a[ks][0], a[ks][1], a[ks][2], a[ks][3],
                         wf[ob][ks][0], wf[ob][ks][1]);
            const int col = oc0 + ob * 8 + 2 * t4;
            *reinterpret_cast<float2*>(&obase[(size_t)r0 * kDO + col]) =
                make_float2(fmaxf(d0, 0.f), fmaxf(d1, 0.f));
            *reinterpret_cast<float2*>(&obase[(size_t)(r0 + 8) * kDO + col]) =
                make_float2(fmaxf(d2, 0.f), fmaxf(d3, 0.f));
        }
    }
}

} // namespace

extern "C" void kernel_launch(void* const* d_in, const int* in_sizes, int n_in,
                              void* d_out, int out_size) {
    (void)in_sizes; (void)n_in; (void)out_size;
    const float* x = (const float*)d_in[0];
    const float* v = (const float*)d_in[1];
    const float* W = (const float*)d_in[2];
    float* out = (float*)d_out;

    cudaFuncSetAttribute(lowrank_inr_kernel,
                         cudaFuncAttributeMaxDynamicSharedMemorySize, SMEM_BYTES);
    lowrank_inr_kernel<<<kB * (kN / TM), THREADS, SMEM_BYTES>>>(x, v, W, out);
}